// round 1
// baseline (speedup 1.0000x reference)
#include <cuda_runtime.h>
#include <math.h>

#define B_ 2
#define T_ 2048
#define D_ 1024
#define H_ 16
#define DH_ 64
#define SCALE_ 0.03125f     /* 1/sqrt(1024) exactly */
#define NEG_ -65504.0f

typedef unsigned long long u64;

// Scratch (static device globals — no allocation in kernel_launch)
__device__ float g_Q[B_*H_*T_*DH_];
__device__ float g_K[B_*H_*T_*DH_];
__device__ float g_V[B_*H_*T_*DH_];
__device__ float g_CTX[(size_t)B_*T_*D_];

// ---- packed f32x2 helpers (FFMA2: 2x fp32 throughput on sm_103a) ----
__device__ __forceinline__ void ffma2(u64& c, u64 a, u64 b) {
    asm("fma.rn.f32x2 %0, %1, %2, %0;" : "+l"(c) : "l"(a), "l"(b));
}
__device__ __forceinline__ u64 pack2(float lo, float hi) {
    u64 r; asm("mov.b64 %0, {%1, %2};" : "=l"(r) : "f"(lo), "f"(hi)); return r;
}
__device__ __forceinline__ void unpack2(u64 v, float& lo, float& hi) {
    asm("mov.b64 {%0, %1}, %2;" : "=f"(lo), "=f"(hi) : "l"(v));
}
__device__ __forceinline__ u64 mul2(u64 a, u64 b) {
    u64 r; asm("mul.rn.f32x2 %0, %1, %2;" : "=l"(r) : "l"(a), "l"(b)); return r;
}

__device__ __forceinline__ float redmax16(float v) {
    v = fmaxf(v, __shfl_xor_sync(0xffffffffu, v, 1));
    v = fmaxf(v, __shfl_xor_sync(0xffffffffu, v, 2));
    v = fmaxf(v, __shfl_xor_sync(0xffffffffu, v, 4));
    v = fmaxf(v, __shfl_xor_sync(0xffffffffu, v, 8));
    return v;
}
__device__ __forceinline__ float redsum16(float v) {
    v += __shfl_xor_sync(0xffffffffu, v, 1);
    v += __shfl_xor_sync(0xffffffffu, v, 2);
    v += __shfl_xor_sync(0xffffffffu, v, 4);
    v += __shfl_xor_sync(0xffffffffu, v, 8);
    return v;
}

// ============================================================================
// GEMM: Y = X(4096x1024) @ W(1024x1024) + bias
// scatter=1: write Y into [B,H,T,64] layout (for QKV projections)
// scatter=0: write Y row-major [4096,1024]   (for output projection)
// Block: 64x64 tile, 256 threads, 4x4 micro-tile per thread, FFMA2 inner loop.
// ============================================================================
__global__ void __launch_bounds__(256) gemm64(
    const float* __restrict__ X, const float* __restrict__ W,
    const float* __restrict__ bias, float* __restrict__ Y, int scatter)
{
    __shared__ __align__(16) float As2[16][136];  // k-major, duplicate-packed rows
    __shared__ __align__(16) float Bs[16][64];

    const int tid = threadIdx.x;
    const int tx = tid & 15, ty = tid >> 4;
    const int m0 = blockIdx.y << 6, n0 = blockIdx.x << 6;

    u64 c2[4][2];
    #pragma unroll
    for (int i = 0; i < 4; i++) { c2[i][0] = 0ull; c2[i][1] = 0ull; }

    const int arow = tid >> 2;           // 0..63
    const int akc  = (tid & 3) << 2;     // 0,4,8,12
    const int brow = tid >> 4;           // 0..15
    const int bcol = (tid & 15) << 2;    // 0..60

    const float* Xp = X + (size_t)(m0 + arow) * D_ + akc;
    const float* Wp = W + (size_t)brow * D_ + n0 + bcol;

    for (int kt = 0; kt < D_ / 16; kt++) {
        float4 av = *(const float4*)(Xp + kt * 16);
        float4 bv = *(const float4*)(Wp + (size_t)kt * 16 * D_);
        *(float2*)&As2[akc+0][2*arow] = make_float2(av.x, av.x);
        *(float2*)&As2[akc+1][2*arow] = make_float2(av.y, av.y);
        *(float2*)&As2[akc+2][2*arow] = make_float2(av.z, av.z);
        *(float2*)&As2[akc+3][2*arow] = make_float2(av.w, av.w);
        *(float4*)&Bs[brow][bcol] = bv;
        __syncthreads();
        #pragma unroll
        for (int kk = 0; kk < 16; kk++) {
            ulonglong2 a01 = *(const ulonglong2*)&As2[kk][8*ty];
            ulonglong2 a23 = *(const ulonglong2*)&As2[kk][8*ty + 4];
            ulonglong2 bb  = *(const ulonglong2*)&Bs[kk][4*tx];
            ffma2(c2[0][0], a01.x, bb.x); ffma2(c2[0][1], a01.x, bb.y);
            ffma2(c2[1][0], a01.y, bb.x); ffma2(c2[1][1], a01.y, bb.y);
            ffma2(c2[2][0], a23.x, bb.x); ffma2(c2[2][1], a23.x, bb.y);
            ffma2(c2[3][0], a23.y, bb.x); ffma2(c2[3][1], a23.y, bb.y);
        }
        __syncthreads();
    }

    const int ncol = n0 + 4*tx;
    float4 b4 = *(const float4*)(bias + ncol);
    #pragma unroll
    for (int i = 0; i < 4; i++) {
        float r0, r1, r2, r3;
        unpack2(c2[i][0], r0, r1);
        unpack2(c2[i][1], r2, r3);
        float4 r = make_float4(r0 + b4.x, r1 + b4.y, r2 + b4.z, r3 + b4.w);
        int m = m0 + 4*ty + i;
        if (scatter) {
            int bb_ = m >> 11, t = m & (T_ - 1);     // m = b*T + t
            int h = n0 >> 6;                          // 64-col tile == one head
            *(float4*)&Y[(((size_t)(bb_*H_ + h) * T_ + t) << 6) + 4*tx] = r;
        } else {
            *(float4*)&Y[(size_t)m * D_ + ncol] = r;
        }
    }
}

// ============================================================================
// Fused flash attention: per (q-tile of 64, head, batch).
// Score GEMM (64x64x64) -> mask -> online softmax -> PV GEMM (64x64x64).
// All inner loops FFMA2-packed via duplicate-packed shared operands.
// ============================================================================
#define QS2_OFF 0
#define KS_OFF  (64*136)
#define VS_OFF  (KS_OFF + 64*68)
#define PS2_OFF (VS_OFF + 64*68)
#define MSK_OFF (PS2_OFF + 64*136)
#define SMEM_FLOATS (MSK_OFF + 64)

__global__ void __launch_bounds__(256) attn_kernel(const int* __restrict__ mask)
{
    extern __shared__ __align__(16) float sm[];
    float* Qs2 = sm + QS2_OFF;   // [d][2*q]  dup-packed, stride 136
    float* Ks  = sm + KS_OFF;    // [d][key]  transposed,  stride 68
    float* Vs  = sm + VS_OFF;    // [key][d]  natural,     stride 68
    float* Ps2 = sm + PS2_OFF;   // [key][2*q] dup-packed, stride 136
    float* msk = sm + MSK_OFF;   // [64]

    const int tid = threadIdx.x;
    const int tx = tid & 15, ty = tid >> 4;
    const int qt0 = blockIdx.x << 6;
    const int h = blockIdx.y, b = blockIdx.z;
    const size_t bh = (size_t)(b * H_ + h) * T_ * DH_;
    const float* Qg = g_Q + bh;
    const float* Kg = g_K + bh;
    const float* Vg = g_V + bh;

    // Load Q tile, transpose + duplicate-pack (once per block)
    #pragma unroll
    for (int rep = 0; rep < 4; rep++) {
        int idx = tid + rep * 256;
        int qi = idx >> 4;
        int d4 = (idx & 15) << 2;
        float4 v = *(const float4*)(Qg + (size_t)(qt0 + qi) * DH_ + d4);
        *(float2*)&Qs2[(d4+0)*136 + 2*qi] = make_float2(v.x, v.x);
        *(float2*)&Qs2[(d4+1)*136 + 2*qi] = make_float2(v.y, v.y);
        *(float2*)&Qs2[(d4+2)*136 + 2*qi] = make_float2(v.z, v.z);
        *(float2*)&Qs2[(d4+3)*136 + 2*qi] = make_float2(v.w, v.w);
    }

    float mrun[4], lrun[4];
    u64 o2[4][2];
    #pragma unroll
    for (int i = 0; i < 4; i++) {
        mrun[i] = -INFINITY; lrun[i] = 0.f;
        o2[i][0] = 0ull; o2[i][1] = 0ull;
    }
    __syncthreads();

    for (int kt = 0; kt < T_ / 64; kt++) {
        const int k0 = kt << 6;
        // Load K (transposed) and V (natural) tiles
        #pragma unroll
        for (int rep = 0; rep < 4; rep++) {
            int idx = tid + rep * 256;
            int kj = idx >> 4;
            int d4 = (idx & 15) << 2;
            float4 kv = *(const float4*)(Kg + (size_t)(k0 + kj) * DH_ + d4);
            Ks[(d4+0)*68 + kj] = kv.x;
            Ks[(d4+1)*68 + kj] = kv.y;
            Ks[(d4+2)*68 + kj] = kv.z;
            Ks[(d4+3)*68 + kj] = kv.w;
            float4 vv = *(const float4*)(Vg + (size_t)(k0 + kj) * DH_ + d4);
            *(float4*)&Vs[kj*68 + d4] = vv;
        }
        if (tid < 64) msk[tid] = (mask[b * T_ + k0 + tid] == 0) ? 0.f : 1.f;
        __syncthreads();

        // ---- S = Q @ K^T (per-thread 4 rows x 4 keys) ----
        u64 s2[4][2];
        #pragma unroll
        for (int i = 0; i < 4; i++) { s2[i][0] = 0ull; s2[i][1] = 0ull; }
        #pragma unroll 8
        for (int kk = 0; kk < 64; kk++) {
            ulonglong2 a01 = *(const ulonglong2*)&Qs2[kk*136 + 8*ty];
            ulonglong2 a23 = *(const ulonglong2*)&Qs2[kk*136 + 8*ty + 4];
            ulonglong2 bb  = *(const ulonglong2*)&Ks[kk*68 + 4*tx];
            ffma2(s2[0][0], a01.x, bb.x); ffma2(s2[0][1], a01.x, bb.y);
            ffma2(s2[1][0], a01.y, bb.x); ffma2(s2[1][1], a01.y, bb.y);
            ffma2(s2[2][0], a23.x, bb.x); ffma2(s2[2][1], a23.x, bb.y);
            ffma2(s2[3][0], a23.y, bb.x); ffma2(s2[3][1], a23.y, bb.y);
        }

        // ---- scale + mask + online softmax ----
        float mk0 = msk[4*tx+0], mk1 = msk[4*tx+1];
        float mk2 = msk[4*tx+2], mk3 = msk[4*tx+3];
        #pragma unroll
        for (int i = 0; i < 4; i++) {
            float s0, s1, s2f, s3f;
            unpack2(s2[i][0], s0, s1);
            unpack2(s2[i][1], s2f, s3f);
            s0  = (mk0 != 0.f) ? s0  * SCALE_ : NEG_;
            s1  = (mk1 != 0.f) ? s1  * SCALE_ : NEG_;
            s2f = (mk2 != 0.f) ? s2f * SCALE_ : NEG_;
            s3f = (mk3 != 0.f) ? s3f * SCALE_ : NEG_;
            float rm = fmaxf(fmaxf(s0, s1), fmaxf(s2f, s3f));
            rm = redmax16(rm);
            float mnew = fmaxf(mrun[i], rm);
            float alpha = __expf(mrun[i] - mnew);
            float p0 = __expf(s0  - mnew);
            float p1 = __expf(s1  - mnew);
            float p2 = __expf(s2f - mnew);
            float p3 = __expf(s3f - mnew);
            float rs = redsum16(p0 + p1 + p2 + p3);
            lrun[i] = lrun[i] * alpha + rs;
            mrun[i] = mnew;
            u64 al2 = pack2(alpha, alpha);
            o2[i][0] = mul2(o2[i][0], al2);
            o2[i][1] = mul2(o2[i][1], al2);
            int qrow2 = 2 * (4*ty + i);
            *(float2*)&Ps2[(4*tx+0)*136 + qrow2] = make_float2(p0, p0);
            *(float2*)&Ps2[(4*tx+1)*136 + qrow2] = make_float2(p1, p1);
            *(float2*)&Ps2[(4*tx+2)*136 + qrow2] = make_float2(p2, p2);
            *(float2*)&Ps2[(4*tx+3)*136 + qrow2] = make_float2(p3, p3);
        }
        __syncthreads();

        // ---- O += P @ V (rows = queries, cols = head dims) ----
        #pragma unroll 8
        for (int kk = 0; kk < 64; kk++) {
            ulonglong2 a01 = *(const ulonglong2*)&Ps2[kk*136 + 8*ty];
            ulonglong2 a23 = *(const ulonglong2*)&Ps2[kk*136 + 8*ty + 4];
            ulonglong2 bb  = *(const ulonglong2*)&Vs[kk*68 + 4*tx];
            ffma2(o2[0][0], a01.x, bb.x); ffma2(o2[0][1], a01.x, bb.y);
            ffma2(o2[1][0], a01.y, bb.x); ffma2(o2[1][1], a01.y, bb.y);
            ffma2(o2[2][0], a23.x, bb.x); ffma2(o2[2][1], a23.x, bb.y);
            ffma2(o2[3][0], a23.y, bb.x); ffma2(o2[3][1], a23.y, bb.y);
        }
        __syncthreads();
    }

    // ---- normalize + write context ----
    #pragma unroll
    for (int i = 0; i < 4; i++) {
        float inv = 1.0f / lrun[i];
        float o0, o1, oA, oB;
        unpack2(o2[i][0], o0, o1);
        unpack2(o2[i][1], oA, oB);
        int t = qt0 + 4*ty + i;
        float4 r = make_float4(o0 * inv, o1 * inv, oA * inv, oB * inv);
        *(float4*)&g_CTX[(size_t)(b * T_ + t) * D_ + h * DH_ + 4*tx] = r;
    }
}

// ============================================================================
extern "C" void kernel_launch(void* const* d_in, const int* in_sizes, int n_in,
                              void* d_out, int out_size)
{
    const float* q  = (const float*)d_in[0];
    const float* k  = (const float*)d_in[1];
    const float* v  = (const float*)d_in[2];
    const int*  mk  = (const int*)  d_in[3];
    const float* Wq = (const float*)d_in[4];
    const float* bq = (const float*)d_in[5];
    const float* Wk = (const float*)d_in[6];
    const float* bk = (const float*)d_in[7];
    const float* Wv = (const float*)d_in[8];
    const float* bv = (const float*)d_in[9];
    const float* Wo = (const float*)d_in[10];
    const float* bo = (const float*)d_in[11];
    float* out = (float*)d_out;

    float *pQ, *pK, *pV, *pC;
    cudaGetSymbolAddress((void**)&pQ, g_Q);
    cudaGetSymbolAddress((void**)&pK, g_K);
    cudaGetSymbolAddress((void**)&pV, g_V);
    cudaGetSymbolAddress((void**)&pC, g_CTX);

    size_t shmem = (size_t)SMEM_FLOATS * sizeof(float);   // ~104.7 KB
    cudaFuncSetAttribute(attn_kernel,
                         cudaFuncAttributeMaxDynamicSharedMemorySize, (int)shmem);

    dim3 blk(256);
    dim3 gp(D_ / 64, (B_ * T_) / 64);   // (16, 64)
    gemm64<<<gp, blk>>>(q, Wq, bq, pQ, 1);
    gemm64<<<gp, blk>>>(k, Wk, bk, pK, 1);
    gemm64<<<gp, blk>>>(v, Wv, bv, pV, 1);
    attn_kernel<<<dim3(T_ / 64, H_, B_), blk, shmem>>>(mk);
    gemm64<<<gp, blk>>>(pC, Wo, bo, out, 0);
}

// round 2
// speedup vs baseline: 1.0006x; 1.0006x over previous
#include <cuda_runtime.h>
#include <math.h>

#define B_ 2
#define T_ 2048
#define D_ 1024
#define H_ 16
#define DH_ 64
#define SCALE_ 0.03125f     /* 1/sqrt(1024) exactly */
#define NEG_ -65504.0f

typedef unsigned long long u64;

// Scratch (static device globals — no allocation in kernel_launch)
__device__ float g_Q[B_*H_*T_*DH_];
__device__ float g_K[B_*H_*T_*DH_];
__device__ float g_V[B_*H_*T_*DH_];
__device__ float g_CTX[(size_t)B_*T_*D_];

// ---- packed f32x2 helpers (FFMA2: 2x fp32 throughput on sm_103a) ----
__device__ __forceinline__ void ffma2(u64& c, u64 a, u64 b) {
    asm("fma.rn.f32x2 %0, %1, %2, %0;" : "+l"(c) : "l"(a), "l"(b));
}
__device__ __forceinline__ u64 pack2(float lo, float hi) {
    u64 r; asm("mov.b64 %0, {%1, %2};" : "=l"(r) : "f"(lo), "f"(hi)); return r;
}
__device__ __forceinline__ void unpack2(u64 v, float& lo, float& hi) {
    asm("mov.b64 {%0, %1}, %2;" : "=f"(lo), "=f"(hi) : "l"(v));
}
__device__ __forceinline__ u64 mul2(u64 a, u64 b) {
    u64 r; asm("mul.rn.f32x2 %0, %1, %2;" : "=l"(r) : "l"(a), "l"(b)); return r;
}

__device__ __forceinline__ float redmax16(float v) {
    v = fmaxf(v, __shfl_xor_sync(0xffffffffu, v, 1));
    v = fmaxf(v, __shfl_xor_sync(0xffffffffu, v, 2));
    v = fmaxf(v, __shfl_xor_sync(0xffffffffu, v, 4));
    v = fmaxf(v, __shfl_xor_sync(0xffffffffu, v, 8));
    return v;
}
__device__ __forceinline__ float redsum16(float v) {
    v += __shfl_xor_sync(0xffffffffu, v, 1);
    v += __shfl_xor_sync(0xffffffffu, v, 2);
    v += __shfl_xor_sync(0xffffffffu, v, 4);
    v += __shfl_xor_sync(0xffffffffu, v, 8);
    return v;
}

// ============================================================================
// GEMM: Y = X(4096x1024) @ W(1024x1024) + bias
// scatter=1: write Y into [B,H,T,64] layout (for QKV projections)
// scatter=0: write Y row-major [4096,1024]   (for output projection)
// Block: 64x64 tile, 256 threads, 4x4 micro-tile per thread, FFMA2 inner loop.
// ============================================================================
__global__ void __launch_bounds__(256) gemm64(
    const float* __restrict__ X, const float* __restrict__ W,
    const float* __restrict__ bias, float* __restrict__ Y, int scatter)
{
    __shared__ __align__(16) float As2[16][136];  // k-major, duplicate-packed rows
    __shared__ __align__(16) float Bs[16][64];

    const int tid = threadIdx.x;
    const int tx = tid & 15, ty = tid >> 4;
    const int m0 = blockIdx.y << 6, n0 = blockIdx.x << 6;

    u64 c2[4][2];
    #pragma unroll
    for (int i = 0; i < 4; i++) { c2[i][0] = 0ull; c2[i][1] = 0ull; }

    const int arow = tid >> 2;           // 0..63
    const int akc  = (tid & 3) << 2;     // 0,4,8,12
    const int brow = tid >> 4;           // 0..15
    const int bcol = (tid & 15) << 2;    // 0..60

    const float* Xp = X + (size_t)(m0 + arow) * D_ + akc;
    const float* Wp = W + (size_t)brow * D_ + n0 + bcol;

    for (int kt = 0; kt < D_ / 16; kt++) {
        float4 av = *(const float4*)(Xp + kt * 16);
        float4 bv = *(const float4*)(Wp + (size_t)kt * 16 * D_);
        *(float2*)&As2[akc+0][2*arow] = make_float2(av.x, av.x);
        *(float2*)&As2[akc+1][2*arow] = make_float2(av.y, av.y);
        *(float2*)&As2[akc+2][2*arow] = make_float2(av.z, av.z);
        *(float2*)&As2[akc+3][2*arow] = make_float2(av.w, av.w);
        *(float4*)&Bs[brow][bcol] = bv;
        __syncthreads();
        #pragma unroll
        for (int kk = 0; kk < 16; kk++) {
            ulonglong2 a01 = *(const ulonglong2*)&As2[kk][8*ty];
            ulonglong2 a23 = *(const ulonglong2*)&As2[kk][8*ty + 4];
            ulonglong2 bb  = *(const ulonglong2*)&Bs[kk][4*tx];
            ffma2(c2[0][0], a01.x, bb.x); ffma2(c2[0][1], a01.x, bb.y);
            ffma2(c2[1][0], a01.y, bb.x); ffma2(c2[1][1], a01.y, bb.y);
            ffma2(c2[2][0], a23.x, bb.x); ffma2(c2[2][1], a23.x, bb.y);
            ffma2(c2[3][0], a23.y, bb.x); ffma2(c2[3][1], a23.y, bb.y);
        }
        __syncthreads();
    }

    const int ncol = n0 + 4*tx;
    float4 b4 = *(const float4*)(bias + ncol);
    #pragma unroll
    for (int i = 0; i < 4; i++) {
        float r0, r1, r2, r3;
        unpack2(c2[i][0], r0, r1);
        unpack2(c2[i][1], r2, r3);
        float4 r = make_float4(r0 + b4.x, r1 + b4.y, r2 + b4.z, r3 + b4.w);
        int m = m0 + 4*ty + i;
        if (scatter) {
            int bb_ = m >> 11, t = m & (T_ - 1);     // m = b*T + t
            int h = n0 >> 6;                          // 64-col tile == one head
            *(float4*)&Y[(((size_t)(bb_*H_ + h) * T_ + t) << 6) + 4*tx] = r;
        } else {
            *(float4*)&Y[(size_t)m * D_ + ncol] = r;
        }
    }
}

// ============================================================================
// Fused flash attention: per (q-tile of 64, head, batch).
// Score GEMM (64x64x64) -> mask -> online softmax -> PV GEMM (64x64x64).
// All inner loops FFMA2-packed via duplicate-packed shared operands.
// ============================================================================
#define QS2_OFF 0
#define KS_OFF  (64*136)
#define VS_OFF  (KS_OFF + 64*68)
#define PS2_OFF (VS_OFF + 64*68)
#define MSK_OFF (PS2_OFF + 64*136)
#define SMEM_FLOATS (MSK_OFF + 64)

__global__ void __launch_bounds__(256) attn_kernel(const int* __restrict__ mask)
{
    extern __shared__ __align__(16) float sm[];
    float* Qs2 = sm + QS2_OFF;   // [d][2*q]  dup-packed, stride 136
    float* Ks  = sm + KS_OFF;    // [d][key]  transposed,  stride 68
    float* Vs  = sm + VS_OFF;    // [key][d]  natural,     stride 68
    float* Ps2 = sm + PS2_OFF;   // [key][2*q] dup-packed, stride 136
    float* msk = sm + MSK_OFF;   // [64]

    const int tid = threadIdx.x;
    const int tx = tid & 15, ty = tid >> 4;
    const int qt0 = blockIdx.x << 6;
    const int h = blockIdx.y, b = blockIdx.z;
    const size_t bh = (size_t)(b * H_ + h) * T_ * DH_;
    const float* Qg = g_Q + bh;
    const float* Kg = g_K + bh;
    const float* Vg = g_V + bh;

    // Load Q tile, transpose + duplicate-pack (once per block)
    #pragma unroll
    for (int rep = 0; rep < 4; rep++) {
        int idx = tid + rep * 256;
        int qi = idx >> 4;
        int d4 = (idx & 15) << 2;
        float4 v = *(const float4*)(Qg + (size_t)(qt0 + qi) * DH_ + d4);
        *(float2*)&Qs2[(d4+0)*136 + 2*qi] = make_float2(v.x, v.x);
        *(float2*)&Qs2[(d4+1)*136 + 2*qi] = make_float2(v.y, v.y);
        *(float2*)&Qs2[(d4+2)*136 + 2*qi] = make_float2(v.z, v.z);
        *(float2*)&Qs2[(d4+3)*136 + 2*qi] = make_float2(v.w, v.w);
    }

    float mrun[4], lrun[4];
    u64 o2[4][2];
    #pragma unroll
    for (int i = 0; i < 4; i++) {
        mrun[i] = -INFINITY; lrun[i] = 0.f;
        o2[i][0] = 0ull; o2[i][1] = 0ull;
    }
    __syncthreads();

    for (int kt = 0; kt < T_ / 64; kt++) {
        const int k0 = kt << 6;
        // Load K (transposed) and V (natural) tiles
        #pragma unroll
        for (int rep = 0; rep < 4; rep++) {
            int idx = tid + rep * 256;
            int kj = idx >> 4;
            int d4 = (idx & 15) << 2;
            float4 kv = *(const float4*)(Kg + (size_t)(k0 + kj) * DH_ + d4);
            Ks[(d4+0)*68 + kj] = kv.x;
            Ks[(d4+1)*68 + kj] = kv.y;
            Ks[(d4+2)*68 + kj] = kv.z;
            Ks[(d4+3)*68 + kj] = kv.w;
            float4 vv = *(const float4*)(Vg + (size_t)(k0 + kj) * DH_ + d4);
            *(float4*)&Vs[kj*68 + d4] = vv;
        }
        if (tid < 64) msk[tid] = (mask[b * T_ + k0 + tid] == 0) ? 0.f : 1.f;
        __syncthreads();

        // ---- S = Q @ K^T (per-thread 4 rows x 4 keys) ----
        u64 s2[4][2];
        #pragma unroll
        for (int i = 0; i < 4; i++) { s2[i][0] = 0ull; s2[i][1] = 0ull; }
        #pragma unroll 8
        for (int kk = 0; kk < 64; kk++) {
            ulonglong2 a01 = *(const ulonglong2*)&Qs2[kk*136 + 8*ty];
            ulonglong2 a23 = *(const ulonglong2*)&Qs2[kk*136 + 8*ty + 4];
            ulonglong2 bb  = *(const ulonglong2*)&Ks[kk*68 + 4*tx];
            ffma2(s2[0][0], a01.x, bb.x); ffma2(s2[0][1], a01.x, bb.y);
            ffma2(s2[1][0], a01.y, bb.x); ffma2(s2[1][1], a01.y, bb.y);
            ffma2(s2[2][0], a23.x, bb.x); ffma2(s2[2][1], a23.x, bb.y);
            ffma2(s2[3][0], a23.y, bb.x); ffma2(s2[3][1], a23.y, bb.y);
        }

        // ---- scale + mask + online softmax ----
        float mk0 = msk[4*tx+0], mk1 = msk[4*tx+1];
        float mk2 = msk[4*tx+2], mk3 = msk[4*tx+3];
        #pragma unroll
        for (int i = 0; i < 4; i++) {
            float s0, s1, s2f, s3f;
            unpack2(s2[i][0], s0, s1);
            unpack2(s2[i][1], s2f, s3f);
            s0  = (mk0 != 0.f) ? s0  * SCALE_ : NEG_;
            s1  = (mk1 != 0.f) ? s1  * SCALE_ : NEG_;
            s2f = (mk2 != 0.f) ? s2f * SCALE_ : NEG_;
            s3f = (mk3 != 0.f) ? s3f * SCALE_ : NEG_;
            float rm = fmaxf(fmaxf(s0, s1), fmaxf(s2f, s3f));
            rm = redmax16(rm);
            float mnew = fmaxf(mrun[i], rm);
            float alpha = __expf(mrun[i] - mnew);
            float p0 = __expf(s0  - mnew);
            float p1 = __expf(s1  - mnew);
            float p2 = __expf(s2f - mnew);
            float p3 = __expf(s3f - mnew);
            float rs = redsum16(p0 + p1 + p2 + p3);
            lrun[i] = lrun[i] * alpha + rs;
            mrun[i] = mnew;
            u64 al2 = pack2(alpha, alpha);
            o2[i][0] = mul2(o2[i][0], al2);
            o2[i][1] = mul2(o2[i][1], al2);
            int qrow2 = 2 * (4*ty + i);
            *(float2*)&Ps2[(4*tx+0)*136 + qrow2] = make_float2(p0, p0);
            *(float2*)&Ps2[(4*tx+1)*136 + qrow2] = make_float2(p1, p1);
            *(float2*)&Ps2[(4*tx+2)*136 + qrow2] = make_float2(p2, p2);
            *(float2*)&Ps2[(4*tx+3)*136 + qrow2] = make_float2(p3, p3);
        }
        __syncthreads();

        // ---- O += P @ V (rows = queries, cols = head dims) ----
        #pragma unroll 8
        for (int kk = 0; kk < 64; kk++) {
            ulonglong2 a01 = *(const ulonglong2*)&Ps2[kk*136 + 8*ty];
            ulonglong2 a23 = *(const ulonglong2*)&Ps2[kk*136 + 8*ty + 4];
            ulonglong2 bb  = *(const ulonglong2*)&Vs[kk*68 + 4*tx];
            ffma2(o2[0][0], a01.x, bb.x); ffma2(o2[0][1], a01.x, bb.y);
            ffma2(o2[1][0], a01.y, bb.x); ffma2(o2[1][1], a01.y, bb.y);
            ffma2(o2[2][0], a23.x, bb.x); ffma2(o2[2][1], a23.x, bb.y);
            ffma2(o2[3][0], a23.y, bb.x); ffma2(o2[3][1], a23.y, bb.y);
        }
        __syncthreads();
    }

    // ---- normalize + write context ----
    #pragma unroll
    for (int i = 0; i < 4; i++) {
        float inv = 1.0f / lrun[i];
        float o0, o1, oA, oB;
        unpack2(o2[i][0], o0, o1);
        unpack2(o2[i][1], oA, oB);
        int t = qt0 + 4*ty + i;
        float4 r = make_float4(o0 * inv, o1 * inv, oA * inv, oB * inv);
        *(float4*)&g_CTX[(size_t)(b * T_ + t) * D_ + h * DH_ + 4*tx] = r;
    }
}

// ============================================================================
extern "C" void kernel_launch(void* const* d_in, const int* in_sizes, int n_in,
                              void* d_out, int out_size)
{
    const float* q  = (const float*)d_in[0];
    const float* k  = (const float*)d_in[1];
    const float* v  = (const float*)d_in[2];
    const int*  mk  = (const int*)  d_in[3];
    const float* Wq = (const float*)d_in[4];
    const float* bq = (const float*)d_in[5];
    const float* Wk = (const float*)d_in[6];
    const float* bk = (const float*)d_in[7];
    const float* Wv = (const float*)d_in[8];
    const float* bv = (const float*)d_in[9];
    const float* Wo = (const float*)d_in[10];
    const float* bo = (const float*)d_in[11];
    float* out = (float*)d_out;

    float *pQ, *pK, *pV, *pC;
    cudaGetSymbolAddress((void**)&pQ, g_Q);
    cudaGetSymbolAddress((void**)&pK, g_K);
    cudaGetSymbolAddress((void**)&pV, g_V);
    cudaGetSymbolAddress((void**)&pC, g_CTX);

    size_t shmem = (size_t)SMEM_FLOATS * sizeof(float);   // ~104.7 KB
    cudaFuncSetAttribute(attn_kernel,
                         cudaFuncAttributeMaxDynamicSharedMemorySize, (int)shmem);

    dim3 blk(256);
    dim3 gp(D_ / 64, (B_ * T_) / 64);   // (16, 64)
    gemm64<<<gp, blk>>>(q, Wq, bq, pQ, 1);
    gemm64<<<gp, blk>>>(k, Wk, bk, pK, 1);
    gemm64<<<gp, blk>>>(v, Wv, bv, pV, 1);
    attn_kernel<<<dim3(T_ / 64, H_, B_), blk, shmem>>>(mk);
    gemm64<<<gp, blk>>>(pC, Wo, bo, out, 0);
}

// round 4
// speedup vs baseline: 2.1050x; 2.1037x over previous
#include <cuda_runtime.h>
#include <cuda_bf16.h>
#include <math.h>
#include <stdint.h>

#define B_ 2
#define T_ 2048
#define D_ 1024
#define H_ 16
#define DH_ 64
#define SCALE_ 0.03125f     /* 1/sqrt(1024) exactly */
#define NEG_ -65504.0f

// ============================================================================
// Scratch (static device globals — no allocation in kernel_launch)
// ============================================================================
__device__ float g_CTX[(size_t)B_*T_*D_];
__device__ __nv_bfloat16 g_Ah[(size_t)4096*1024];
__device__ __nv_bfloat16 g_Al[(size_t)4096*1024];
__device__ __nv_bfloat16 g_Wh[(size_t)1024*1024];
__device__ __nv_bfloat16 g_Wl[(size_t)1024*1024];
__device__ __nv_bfloat16 g_Qh[(size_t)B_*H_*T_*DH_];
__device__ __nv_bfloat16 g_Ql[(size_t)B_*H_*T_*DH_];
__device__ __nv_bfloat16 g_Kh[(size_t)B_*H_*T_*DH_];
__device__ __nv_bfloat16 g_Kl[(size_t)B_*H_*T_*DH_];
__device__ __nv_bfloat16 g_Vh[(size_t)B_*H_*T_*DH_];
__device__ __nv_bfloat16 g_Vl[(size_t)B_*H_*T_*DH_];

// ============================================================================
// mma.sync / ldmatrix helpers (base-target PTX: works on compute_103)
// ============================================================================
__device__ __forceinline__ unsigned smem_u32(const void* p) {
    unsigned a;
    asm("{ .reg .u64 t; cvta.to.shared.u64 t, %1; cvt.u32.u64 %0, t; }"
        : "=r"(a) : "l"(p));
    return a;
}
__device__ __forceinline__ void mma_bf(float* c, const unsigned* a, const unsigned* b) {
    asm volatile(
        "mma.sync.aligned.m16n8k16.row.col.f32.bf16.bf16.f32 "
        "{%0,%1,%2,%3}, {%4,%5,%6,%7}, {%8,%9}, {%0,%1,%2,%3};"
        : "+f"(c[0]), "+f"(c[1]), "+f"(c[2]), "+f"(c[3])
        : "r"(a[0]), "r"(a[1]), "r"(a[2]), "r"(a[3]), "r"(b[0]), "r"(b[1]));
}
__device__ __forceinline__ void ldsm4(unsigned* r, unsigned a) {
    asm volatile("ldmatrix.sync.aligned.m8n8.x4.shared.b16 {%0,%1,%2,%3}, [%4];"
        : "=r"(r[0]), "=r"(r[1]), "=r"(r[2]), "=r"(r[3]) : "r"(a));
}
__device__ __forceinline__ void ldsm4t(unsigned* r, unsigned a) {
    asm volatile("ldmatrix.sync.aligned.m8n8.x4.trans.shared.b16 {%0,%1,%2,%3}, [%4];"
        : "=r"(r[0]), "=r"(r[1]), "=r"(r[2]), "=r"(r[3]) : "r"(a));
}

// ============================================================================
// conv_split: fp32 -> (hi, lo) bf16, elementwise, vectorized
// ============================================================================
__global__ void __launch_bounds__(256) conv_split(
    const float* __restrict__ x, __nv_bfloat16* __restrict__ hi,
    __nv_bfloat16* __restrict__ lo, int n4)
{
    int i = blockIdx.x * 256 + threadIdx.x;
    if (i >= n4) return;
    float4 v = ((const float4*)x)[i];
    __nv_bfloat16 h0 = __float2bfloat16_rn(v.x);
    __nv_bfloat16 h1 = __float2bfloat16_rn(v.y);
    __nv_bfloat16 h2 = __float2bfloat16_rn(v.z);
    __nv_bfloat16 h3 = __float2bfloat16_rn(v.w);
    __nv_bfloat162 ha; ha.x = h0; ha.y = h1;
    __nv_bfloat162 hb; hb.x = h2; hb.y = h3;
    __nv_bfloat162 la, lb;
    la.x = __float2bfloat16_rn(v.x - __bfloat162float(h0));
    la.y = __float2bfloat16_rn(v.y - __bfloat162float(h1));
    lb.x = __float2bfloat16_rn(v.z - __bfloat162float(h2));
    lb.y = __float2bfloat16_rn(v.w - __bfloat162float(h3));
    ((__nv_bfloat162*)hi)[2*i]   = ha;
    ((__nv_bfloat162*)hi)[2*i+1] = hb;
    ((__nv_bfloat162*)lo)[2*i]   = la;
    ((__nv_bfloat162*)lo)[2*i+1] = lb;
}

// ============================================================================
// GEMM via mma.sync: Y(4096x1024) = A @ W + bias, split-bf16 3-stream.
// A row-major [m][k]; W row-major [k][n] (B frags via ldmatrix.trans).
// Block tile 128x128, 256 threads, warp grid 2(M)x4(N), warp tile 64x32.
// mode 0: scatter hi/lo bf16 into [B,H,T,64] (projections)
// mode 1: dense fp32 output (out projection)
// ============================================================================
__global__ void __launch_bounds__(256) gemm_mma(
    const __nv_bfloat16* __restrict__ Ah, const __nv_bfloat16* __restrict__ Al,
    const __nv_bfloat16* __restrict__ Wh, const __nv_bfloat16* __restrict__ Wl,
    const float* __restrict__ bias,
    float* __restrict__ Yf,
    __nv_bfloat16* __restrict__ Yh, __nv_bfloat16* __restrict__ Yl,
    int mode)
{
    __shared__ __align__(16) __nv_bfloat16 sA[2][128][40];
    __shared__ __align__(16) __nv_bfloat16 sW[2][32][136];

    const int tid = threadIdx.x, lane = tid & 31, wid = tid >> 5;
    const int wm = wid >> 2, wn = wid & 3;
    const int m0 = blockIdx.y << 7, n0 = blockIdx.x << 7;

    float c[4][4][4];
    #pragma unroll
    for (int i = 0; i < 4; i++)
        #pragma unroll
        for (int j = 0; j < 4; j++)
            #pragma unroll
            for (int e = 0; e < 4; e++) c[i][j][e] = 0.f;

    const int ar = tid >> 1, ac = (tid & 1) << 4;   // A: row, 16-col half
    const int wr = tid >> 3, wc = (tid & 7) << 4;   // W: k-row, 16-col chunk
    const int l15 = lane & 15, lh8 = (lane >> 4) << 3;

    for (int kc = 0; kc < 32; kc++) {
        const int k0 = kc << 5;
        uint4 a0 = *(const uint4*)(Ah + (size_t)(m0 + ar) * 1024 + k0 + ac);
        uint4 a1 = *(const uint4*)(Ah + (size_t)(m0 + ar) * 1024 + k0 + ac + 8);
        uint4 b0 = *(const uint4*)(Al + (size_t)(m0 + ar) * 1024 + k0 + ac);
        uint4 b1 = *(const uint4*)(Al + (size_t)(m0 + ar) * 1024 + k0 + ac + 8);
        uint4 w0 = *(const uint4*)(Wh + (size_t)(k0 + wr) * 1024 + n0 + wc);
        uint4 w1 = *(const uint4*)(Wh + (size_t)(k0 + wr) * 1024 + n0 + wc + 8);
        uint4 x0 = *(const uint4*)(Wl + (size_t)(k0 + wr) * 1024 + n0 + wc);
        uint4 x1 = *(const uint4*)(Wl + (size_t)(k0 + wr) * 1024 + n0 + wc + 8);
        __syncthreads();
        *(uint4*)&sA[0][ar][ac]   = a0;  *(uint4*)&sA[0][ar][ac+8] = a1;
        *(uint4*)&sA[1][ar][ac]   = b0;  *(uint4*)&sA[1][ar][ac+8] = b1;
        *(uint4*)&sW[0][wr][wc]   = w0;  *(uint4*)&sW[0][wr][wc+8] = w1;
        *(uint4*)&sW[1][wr][wc]   = x0;  *(uint4*)&sW[1][wr][wc+8] = x1;
        __syncthreads();

        #pragma unroll
        for (int kk = 0; kk < 32; kk += 16) {
            unsigned a[4][4], bh_[4][2], bl_[4][2], t4[4];
            #pragma unroll
            for (int mi = 0; mi < 4; mi++)
                ldsm4(a[mi], smem_u32(&sA[0][wm*64 + mi*16 + l15][kk + lh8]));
            #pragma unroll
            for (int p = 0; p < 2; p++) {
                ldsm4t(t4, smem_u32(&sW[0][kk + l15][wn*32 + p*16 + lh8]));
                bh_[2*p][0]=t4[0]; bh_[2*p][1]=t4[1];
                bh_[2*p+1][0]=t4[2]; bh_[2*p+1][1]=t4[3];
                ldsm4t(t4, smem_u32(&sW[1][kk + l15][wn*32 + p*16 + lh8]));
                bl_[2*p][0]=t4[0]; bl_[2*p][1]=t4[1];
                bl_[2*p+1][0]=t4[2]; bl_[2*p+1][1]=t4[3];
            }
            #pragma unroll
            for (int mi = 0; mi < 4; mi++)
                #pragma unroll
                for (int ni = 0; ni < 4; ni++) mma_bf(c[mi][ni], a[mi], bh_[ni]);
            #pragma unroll
            for (int mi = 0; mi < 4; mi++)
                #pragma unroll
                for (int ni = 0; ni < 4; ni++) mma_bf(c[mi][ni], a[mi], bl_[ni]);
            #pragma unroll
            for (int mi = 0; mi < 4; mi++)
                ldsm4(a[mi], smem_u32(&sA[1][wm*64 + mi*16 + l15][kk + lh8]));
            #pragma unroll
            for (int mi = 0; mi < 4; mi++)
                #pragma unroll
                for (int ni = 0; ni < 4; ni++) mma_bf(c[mi][ni], a[mi], bh_[ni]);
        }
    }

    // Epilogue
    const int rA = lane >> 2, c2 = (lane & 3) << 1;
    #pragma unroll
    for (int mi = 0; mi < 4; mi++) {
        const int rowA = m0 + wm*64 + mi*16 + rA;
        const int rowB = rowA + 8;
        #pragma unroll
        for (int ni = 0; ni < 4; ni++) {
            const int col = n0 + wn*32 + ni*8 + c2;
            float2 bb = *(const float2*)(bias + col);
            float v00 = c[mi][ni][0] + bb.x, v01 = c[mi][ni][1] + bb.y;
            float v10 = c[mi][ni][2] + bb.x, v11 = c[mi][ni][3] + bb.y;
            if (mode == 0) {
                const int hh = col >> 6, dd = col & 63;
                const int bA = rowA >> 11, tA = rowA & (T_-1);
                const int bB = rowB >> 11, tB = rowB & (T_-1);
                size_t oA = (((size_t)(bA*H_ + hh))*T_ + tA)*64 + dd;
                size_t oB = (((size_t)(bB*H_ + hh))*T_ + tB)*64 + dd;
                __nv_bfloat16 h00 = __float2bfloat16_rn(v00);
                __nv_bfloat16 h01 = __float2bfloat16_rn(v01);
                __nv_bfloat16 h10 = __float2bfloat16_rn(v10);
                __nv_bfloat16 h11 = __float2bfloat16_rn(v11);
                __nv_bfloat162 ph0; ph0.x=h00; ph0.y=h01;
                __nv_bfloat162 ph1; ph1.x=h10; ph1.y=h11;
                __nv_bfloat162 pl0, pl1;
                pl0.x = __float2bfloat16_rn(v00 - __bfloat162float(h00));
                pl0.y = __float2bfloat16_rn(v01 - __bfloat162float(h01));
                pl1.x = __float2bfloat16_rn(v10 - __bfloat162float(h10));
                pl1.y = __float2bfloat16_rn(v11 - __bfloat162float(h11));
                *(__nv_bfloat162*)(Yh + oA) = ph0;
                *(__nv_bfloat162*)(Yl + oA) = pl0;
                *(__nv_bfloat162*)(Yh + oB) = ph1;
                *(__nv_bfloat162*)(Yl + oB) = pl1;
            } else {
                float2 w0; w0.x = v00; w0.y = v01;
                float2 w1; w1.x = v10; w1.y = v11;
                *(float2*)(Yf + (size_t)rowA * 1024 + col) = w0;
                *(float2*)(Yf + (size_t)rowB * 1024 + col) = w1;
            }
        }
    }
}

// ============================================================================
// Flash attention via mma.sync, split-bf16 3-stream, no max subtraction
// (scores bounded: |s*SCALE| <~ 2; masked -> exp(NEG) == 0 exactly).
// Block: 128 queries x (b,h). 256 threads. kt loop over 128-key tiles.
// ============================================================================
#define ATT_QH   0
#define ATT_QL   18432
#define ATT_KH   36864
#define ATT_KL   55296
#define ATT_VH   73728
#define ATT_VL   92160
#define ATT_PH   110592
#define ATT_PL   145408
#define ATT_PSUM 180224
#define ATT_LS   182272
#define ATT_MSK  182784
#define ATT_SMEM 183296

__global__ void __launch_bounds__(256) attn_mma(const int* __restrict__ mask)
{
    extern __shared__ __align__(16) char sm[];
    __nv_bfloat16* sQh = (__nv_bfloat16*)(sm + ATT_QH);
    __nv_bfloat16* sQl = (__nv_bfloat16*)(sm + ATT_QL);
    __nv_bfloat16* sKh = (__nv_bfloat16*)(sm + ATT_KH);
    __nv_bfloat16* sKl = (__nv_bfloat16*)(sm + ATT_KL);
    __nv_bfloat16* sVh = (__nv_bfloat16*)(sm + ATT_VH);
    __nv_bfloat16* sVl = (__nv_bfloat16*)(sm + ATT_VL);
    __nv_bfloat16* sPh = (__nv_bfloat16*)(sm + ATT_PH);
    __nv_bfloat16* sPl = (__nv_bfloat16*)(sm + ATT_PL);
    float* psum = (float*)(sm + ATT_PSUM);
    float* l_s  = (float*)(sm + ATT_LS);
    float* msk  = (float*)(sm + ATT_MSK);

    const int tid = threadIdx.x, lane = tid & 31, wid = tid >> 5;
    const int wm = wid >> 2, wn = wid & 3;
    const int qt0 = blockIdx.x << 7;
    const int hh = blockIdx.y, bb = blockIdx.z;
    const size_t base = ((size_t)(bb*H_ + hh)) * T_ * DH_;

    const int r = tid >> 1, cofs = (tid & 1) << 5;
    const int l15 = lane & 15, lh8 = (lane >> 4) << 3;
    const int bn  = (lane & 7) + ((lane >> 4) << 3), bk8 = ((lane >> 3) & 1) << 3;
    const int rA0 = lane >> 2, c2 = (lane & 3) << 1;

    // Load Q tile (persistent)
    {
        const uint4* s1 = (const uint4*)(g_Qh + base + (size_t)(qt0 + r)*64 + cofs);
        uint4* d1 = (uint4*)(sQh + r*72 + cofs);
        d1[0]=s1[0]; d1[1]=s1[1]; d1[2]=s1[2]; d1[3]=s1[3];
        const uint4* s2 = (const uint4*)(g_Ql + base + (size_t)(qt0 + r)*64 + cofs);
        uint4* d2 = (uint4*)(sQl + r*72 + cofs);
        d2[0]=s2[0]; d2[1]=s2[1]; d2[2]=s2[2]; d2[3]=s2[3];
    }
    if (tid < 128) l_s[tid] = 0.f;

    float o[4][2][4];
    #pragma unroll
    for (int i = 0; i < 4; i++)
        #pragma unroll
        for (int j = 0; j < 2; j++)
            #pragma unroll
            for (int e = 0; e < 4; e++) o[i][j][e] = 0.f;

    for (int kt = 0; kt < 16; kt++) {
        const int k0g = kt << 7;
        // Load K/V tiles
        {
            size_t go = base + (size_t)(k0g + r)*64 + cofs;
            int so = r*72 + cofs;
            const uint4* s1 = (const uint4*)(g_Kh + go);
            uint4* d1 = (uint4*)(sKh + so);
            d1[0]=s1[0]; d1[1]=s1[1]; d1[2]=s1[2]; d1[3]=s1[3];
            const uint4* s2 = (const uint4*)(g_Kl + go);
            uint4* d2 = (uint4*)(sKl + so);
            d2[0]=s2[0]; d2[1]=s2[1]; d2[2]=s2[2]; d2[3]=s2[3];
            const uint4* s3 = (const uint4*)(g_Vh + go);
            uint4* d3 = (uint4*)(sVh + so);
            d3[0]=s3[0]; d3[1]=s3[1]; d3[2]=s3[2]; d3[3]=s3[3];
            const uint4* s4 = (const uint4*)(g_Vl + go);
            uint4* d4 = (uint4*)(sVl + so);
            d4[0]=s4[0]; d4[1]=s4[1]; d4[2]=s4[2]; d4[3]=s4[3];
        }
        if (tid < 128) msk[tid] = (mask[bb*T_ + k0g + tid] == 0) ? 0.f : 1.f;
        __syncthreads();   // (A)

        // ---- S = Q @ K^T ----
        float s[4][4][4];
        #pragma unroll
        for (int i = 0; i < 4; i++)
            #pragma unroll
            for (int j = 0; j < 4; j++)
                #pragma unroll
                for (int e = 0; e < 4; e++) s[i][j][e] = 0.f;

        #pragma unroll
        for (int kk = 0; kk < 64; kk += 16) {
            unsigned a[4][4], bhf[4][2], blf[4][2], t4[4];
            #pragma unroll
            for (int mi = 0; mi < 4; mi++)
                ldsm4(a[mi], smem_u32(&sQh[(wm*64 + mi*16 + l15)*72 + kk + lh8]));
            #pragma unroll
            for (int p = 0; p < 2; p++) {
                ldsm4(t4, smem_u32(&sKh[(wn*32 + p*16 + bn)*72 + kk + bk8]));
                bhf[2*p][0]=t4[0]; bhf[2*p][1]=t4[1];
                bhf[2*p+1][0]=t4[2]; bhf[2*p+1][1]=t4[3];
                ldsm4(t4, smem_u32(&sKl[(wn*32 + p*16 + bn)*72 + kk + bk8]));
                blf[2*p][0]=t4[0]; blf[2*p][1]=t4[1];
                blf[2*p+1][0]=t4[2]; blf[2*p+1][1]=t4[3];
            }
            #pragma unroll
            for (int mi = 0; mi < 4; mi++)
                #pragma unroll
                for (int ni = 0; ni < 4; ni++) mma_bf(s[mi][ni], a[mi], bhf[ni]);
            #pragma unroll
            for (int mi = 0; mi < 4; mi++)
                #pragma unroll
                for (int ni = 0; ni < 4; ni++) mma_bf(s[mi][ni], a[mi], blf[ni]);
            #pragma unroll
            for (int mi = 0; mi < 4; mi++)
                ldsm4(a[mi], smem_u32(&sQl[(wm*64 + mi*16 + l15)*72 + kk + lh8]));
            #pragma unroll
            for (int mi = 0; mi < 4; mi++)
                #pragma unroll
                for (int ni = 0; ni < 4; ni++) mma_bf(s[mi][ni], a[mi], bhf[ni]);
        }

        // ---- p = exp(mask ? s*scale : NEG); row sums; write P hi/lo ----
        #pragma unroll
        for (int mi = 0; mi < 4; mi++) {
            float sumA = 0.f, sumB = 0.f;
            const int rowA = wm*64 + mi*16 + rA0;
            #pragma unroll
            for (int ni = 0; ni < 4; ni++) {
                const int col = wn*32 + ni*8 + c2;
                const float mv0 = msk[col], mv1 = msk[col+1];
                float p00 = __expf(mv0 != 0.f ? s[mi][ni][0]*SCALE_ : NEG_);
                float p01 = __expf(mv1 != 0.f ? s[mi][ni][1]*SCALE_ : NEG_);
                float p10 = __expf(mv0 != 0.f ? s[mi][ni][2]*SCALE_ : NEG_);
                float p11 = __expf(mv1 != 0.f ? s[mi][ni][3]*SCALE_ : NEG_);
                sumA += p00 + p01;  sumB += p10 + p11;
                __nv_bfloat16 h00 = __float2bfloat16_rn(p00);
                __nv_bfloat16 h01 = __float2bfloat16_rn(p01);
                __nv_bfloat16 h10 = __float2bfloat16_rn(p10);
                __nv_bfloat16 h11 = __float2bfloat16_rn(p11);
                __nv_bfloat162 vh0; vh0.x=h00; vh0.y=h01;
                __nv_bfloat162 vh1; vh1.x=h10; vh1.y=h11;
                __nv_bfloat162 vl0, vl1;
                vl0.x = __float2bfloat16_rn(p00 - __bfloat162float(h00));
                vl0.y = __float2bfloat16_rn(p01 - __bfloat162float(h01));
                vl1.x = __float2bfloat16_rn(p10 - __bfloat162float(h10));
                vl1.y = __float2bfloat16_rn(p11 - __bfloat162float(h11));
                *(__nv_bfloat162*)(sPh + rowA*136 + col)      = vh0;
                *(__nv_bfloat162*)(sPh + (rowA+8)*136 + col)  = vh1;
                *(__nv_bfloat162*)(sPl + rowA*136 + col)      = vl0;
                *(__nv_bfloat162*)(sPl + (rowA+8)*136 + col)  = vl1;
            }
            sumA += __shfl_xor_sync(0xffffffffu, sumA, 1);
            sumA += __shfl_xor_sync(0xffffffffu, sumA, 2);
            sumB += __shfl_xor_sync(0xffffffffu, sumB, 1);
            sumB += __shfl_xor_sync(0xffffffffu, sumB, 2);
            if ((lane & 3) == 0) {
                psum[rowA*4 + wn]     = sumA;
                psum[(rowA+8)*4 + wn] = sumB;
            }
        }
        __syncthreads();   // (B)

        if (tid < 128)
            l_s[tid] += psum[tid*4+0] + psum[tid*4+1] + psum[tid*4+2] + psum[tid*4+3];

        // ---- O += P @ V ----
        #pragma unroll
        for (int kk = 0; kk < 128; kk += 16) {
            unsigned pa[4][4], vhf[2][2], vlf[2][2], t4[4];
            #pragma unroll
            for (int mi = 0; mi < 4; mi++)
                ldsm4(pa[mi], smem_u32(&sPh[(wm*64 + mi*16 + l15)*136 + kk + lh8]));
            ldsm4t(t4, smem_u32(&sVh[(kk + l15)*72 + wn*16 + lh8]));
            vhf[0][0]=t4[0]; vhf[0][1]=t4[1]; vhf[1][0]=t4[2]; vhf[1][1]=t4[3];
            ldsm4t(t4, smem_u32(&sVl[(kk + l15)*72 + wn*16 + lh8]));
            vlf[0][0]=t4[0]; vlf[0][1]=t4[1]; vlf[1][0]=t4[2]; vlf[1][1]=t4[3];
            #pragma unroll
            for (int mi = 0; mi < 4; mi++)
                #pragma unroll
                for (int ni = 0; ni < 2; ni++) mma_bf(o[mi][ni], pa[mi], vhf[ni]);
            #pragma unroll
            for (int mi = 0; mi < 4; mi++)
                #pragma unroll
                for (int ni = 0; ni < 2; ni++) mma_bf(o[mi][ni], pa[mi], vlf[ni]);
            #pragma unroll
            for (int mi = 0; mi < 4; mi++)
                ldsm4(pa[mi], smem_u32(&sPl[(wm*64 + mi*16 + l15)*136 + kk + lh8]));
            #pragma unroll
            for (int mi = 0; mi < 4; mi++)
                #pragma unroll
                for (int ni = 0; ni < 2; ni++) mma_bf(o[mi][ni], pa[mi], vhf[ni]);
        }
        __syncthreads();   // (C)
    }

    // ---- normalize + write context (fp32) ----
    #pragma unroll
    for (int mi = 0; mi < 4; mi++) {
        const int rowA = wm*64 + mi*16 + rA0, rowB = rowA + 8;
        const float invA = 1.f / l_s[rowA], invB = 1.f / l_s[rowB];
        #pragma unroll
        for (int ni = 0; ni < 2; ni++) {
            const int col = wn*16 + ni*8 + c2;
            float2 w0; w0.x = o[mi][ni][0]*invA; w0.y = o[mi][ni][1]*invA;
            float2 w1; w1.x = o[mi][ni][2]*invB; w1.y = o[mi][ni][3]*invB;
            *(float2*)(g_CTX + (size_t)(bb*T_ + qt0 + rowA)*D_ + hh*64 + col) = w0;
            *(float2*)(g_CTX + (size_t)(bb*T_ + qt0 + rowB)*D_ + hh*64 + col) = w1;
        }
    }
}

// ============================================================================
extern "C" void kernel_launch(void* const* d_in, const int* in_sizes, int n_in,
                              void* d_out, int out_size)
{
    const float* q  = (const float*)d_in[0];
    const float* k  = (const float*)d_in[1];
    const float* v  = (const float*)d_in[2];
    const int*  mk  = (const int*)  d_in[3];
    const float* Wq = (const float*)d_in[4];
    const float* bq = (const float*)d_in[5];
    const float* Wk = (const float*)d_in[6];
    const float* bk = (const float*)d_in[7];
    const float* Wv = (const float*)d_in[8];
    const float* bv = (const float*)d_in[9];
    const float* Wo = (const float*)d_in[10];
    const float* bo = (const float*)d_in[11];
    float* out = (float*)d_out;

    float* pCTX;
    __nv_bfloat16 *pAh, *pAl, *pWh, *pWl, *pQh, *pQl, *pKh, *pKl, *pVh, *pVl;
    cudaGetSymbolAddress((void**)&pCTX, g_CTX);
    cudaGetSymbolAddress((void**)&pAh, g_Ah);
    cudaGetSymbolAddress((void**)&pAl, g_Al);
    cudaGetSymbolAddress((void**)&pWh, g_Wh);
    cudaGetSymbolAddress((void**)&pWl, g_Wl);
    cudaGetSymbolAddress((void**)&pQh, g_Qh);
    cudaGetSymbolAddress((void**)&pQl, g_Ql);
    cudaGetSymbolAddress((void**)&pKh, g_Kh);
    cudaGetSymbolAddress((void**)&pKl, g_Kl);
    cudaGetSymbolAddress((void**)&pVh, g_Vh);
    cudaGetSymbolAddress((void**)&pVl, g_Vl);

    cudaFuncSetAttribute(attn_mma,
                         cudaFuncAttributeMaxDynamicSharedMemorySize, ATT_SMEM);

    dim3 blk(256);
    dim3 gG(8, 32);

    // Q projection
    conv_split<<<4096, blk>>>(q, pAh, pAl, 1048576);
    conv_split<<<1024, blk>>>(Wq, pWh, pWl, 262144);
    gemm_mma<<<gG, blk>>>(pAh, pAl, pWh, pWl, bq, nullptr, pQh, pQl, 0);
    // K projection
    conv_split<<<4096, blk>>>(k, pAh, pAl, 1048576);
    conv_split<<<1024, blk>>>(Wk, pWh, pWl, 262144);
    gemm_mma<<<gG, blk>>>(pAh, pAl, pWh, pWl, bk, nullptr, pKh, pKl, 0);
    // V projection
    conv_split<<<4096, blk>>>(v, pAh, pAl, 1048576);
    conv_split<<<1024, blk>>>(Wv, pWh, pWl, 262144);
    gemm_mma<<<gG, blk>>>(pAh, pAl, pWh, pWl, bv, nullptr, pVh, pVl, 0);
    // Attention
    attn_mma<<<dim3(16, 16, 2), blk, ATT_SMEM>>>(mk);
    // Output projection
    conv_split<<<4096, blk>>>(pCTX, pAh, pAl, 1048576);
    conv_split<<<1024, blk>>>(Wo, pWh, pWl, 262144);
    gemm_mma<<<gG, blk>>>(pAh, pAl, pWh, pWl, bo, out, nullptr, nullptr, 1);
}

// round 6
// speedup vs baseline: 4.7666x; 2.2644x over previous
#include <cuda_runtime.h>
#include <cuda_bf16.h>
#include <math.h>
#include <stdint.h>

#define B_ 2
#define T_ 2048
#define D_ 1024
#define H_ 16
#define DH_ 64
#define SCALE_ 0.03125f     /* 1/sqrt(1024) exactly */

// ============================================================================
// Scratch (static device globals — no allocation in kernel_launch)
// ============================================================================
__device__ float g_CTX[(size_t)B_*T_*D_];
__device__ __nv_bfloat16 g_Ah[(size_t)4096*1024];
__device__ __nv_bfloat16 g_Al[(size_t)4096*1024];
__device__ __nv_bfloat16 g_Wh[(size_t)1024*1024];
__device__ __nv_bfloat16 g_Wl[(size_t)1024*1024];
__device__ __nv_bfloat16 g_Qh[(size_t)B_*H_*T_*DH_];
__device__ __nv_bfloat16 g_Ql[(size_t)B_*H_*T_*DH_];
__device__ __nv_bfloat16 g_Kh[(size_t)B_*H_*T_*DH_];   // compacted
__device__ __nv_bfloat16 g_Kl[(size_t)B_*H_*T_*DH_];   // compacted
__device__ __nv_bfloat16 g_Vh[(size_t)B_*H_*T_*DH_];   // compacted
__device__ __nv_bfloat16 g_Vl[(size_t)B_*H_*T_*DH_];   // compacted
__device__ int g_pos[B_*T_];
__device__ int g_cnt[B_];

// ============================================================================
// mma.sync / ldmatrix / cp.async helpers (base-target PTX)
// ============================================================================
__device__ __forceinline__ unsigned smem_u32(const void* p) {
    unsigned a;
    asm("{ .reg .u64 t; cvta.to.shared.u64 t, %1; cvt.u32.u64 %0, t; }"
        : "=r"(a) : "l"(p));
    return a;
}
__device__ __forceinline__ void mma_bf(float* c, const unsigned* a, const unsigned* b) {
    asm volatile(
        "mma.sync.aligned.m16n8k16.row.col.f32.bf16.bf16.f32 "
        "{%0,%1,%2,%3}, {%4,%5,%6,%7}, {%8,%9}, {%0,%1,%2,%3};"
        : "+f"(c[0]), "+f"(c[1]), "+f"(c[2]), "+f"(c[3])
        : "r"(a[0]), "r"(a[1]), "r"(a[2]), "r"(a[3]), "r"(b[0]), "r"(b[1]));
}
__device__ __forceinline__ void ldsm4(unsigned* r, unsigned a) {
    asm volatile("ldmatrix.sync.aligned.m8n8.x4.shared.b16 {%0,%1,%2,%3}, [%4];"
        : "=r"(r[0]), "=r"(r[1]), "=r"(r[2]), "=r"(r[3]) : "r"(a));
}
__device__ __forceinline__ void ldsm4t(unsigned* r, unsigned a) {
    asm volatile("ldmatrix.sync.aligned.m8n8.x4.trans.shared.b16 {%0,%1,%2,%3}, [%4];"
        : "=r"(r[0]), "=r"(r[1]), "=r"(r[2]), "=r"(r[3]) : "r"(a));
}
#define CP16(dst_u32, src_ptr) \
    asm volatile("cp.async.cg.shared.global [%0], [%1], 16;" \
        :: "r"(dst_u32), "l"(src_ptr) : "memory")
#define CP_COMMIT() asm volatile("cp.async.commit_group;" ::: "memory")
#define CP_WAIT1()  asm volatile("cp.async.wait_group 1;"  ::: "memory")

// ============================================================================
// scan_mask: per-batch exclusive prefix scan of mask -> compact positions
// ============================================================================
__global__ void __launch_bounds__(1024) scan_mask(const int* __restrict__ mask)
{
    __shared__ int ps[1024];
    const int b = blockIdx.x, i = threadIdx.x;
    const int a0 = (mask[b*T_ + 2*i]     != 0);
    const int a1 = (mask[b*T_ + 2*i + 1] != 0);
    ps[i] = a0 + a1;
    __syncthreads();
    for (int off = 1; off < 1024; off <<= 1) {
        int v = ps[i] + ((i >= off) ? ps[i - off] : 0);
        __syncthreads();
        ps[i] = v;
        __syncthreads();
    }
    const int excl = (i > 0) ? ps[i-1] : 0;
    g_pos[b*T_ + 2*i]     = a0 ? excl : -1;
    g_pos[b*T_ + 2*i + 1] = a1 ? (excl + a0) : -1;
    if (i == 1023) g_cnt[b] = ps[1023];
}

// ============================================================================
// conv_split: fp32 -> (hi, lo) bf16, elementwise, vectorized
// ============================================================================
__global__ void __launch_bounds__(256) conv_split(
    const float* __restrict__ x, __nv_bfloat16* __restrict__ hi,
    __nv_bfloat16* __restrict__ lo, int n4)
{
    int i = blockIdx.x * 256 + threadIdx.x;
    if (i >= n4) return;
    float4 v = ((const float4*)x)[i];
    __nv_bfloat16 h0 = __float2bfloat16_rn(v.x);
    __nv_bfloat16 h1 = __float2bfloat16_rn(v.y);
    __nv_bfloat16 h2 = __float2bfloat16_rn(v.z);
    __nv_bfloat16 h3 = __float2bfloat16_rn(v.w);
    __nv_bfloat162 ha; ha.x = h0; ha.y = h1;
    __nv_bfloat162 hb; hb.x = h2; hb.y = h3;
    __nv_bfloat162 la, lb;
    la.x = __float2bfloat16_rn(v.x - __bfloat162float(h0));
    la.y = __float2bfloat16_rn(v.y - __bfloat162float(h1));
    lb.x = __float2bfloat16_rn(v.z - __bfloat162float(h2));
    lb.y = __float2bfloat16_rn(v.w - __bfloat162float(h3));
    ((__nv_bfloat162*)hi)[2*i]   = ha;
    ((__nv_bfloat162*)hi)[2*i+1] = hb;
    ((__nv_bfloat162*)lo)[2*i]   = la;
    ((__nv_bfloat162*)lo)[2*i+1] = lb;
}

// ============================================================================
// GEMM via mma.sync: Y(4096x1024) = A @ W + bias, split-bf16 3-stream.
// mode 0: Q projection  -> bf16 hi+lo, scatter [B,H,T,64]
// mode 1: K/V projection-> bf16 hi+lo, scatter to COMPACTED rows (pos)
// mode 2: dense fp32 output (out projection)
// ============================================================================
__global__ void __launch_bounds__(256) gemm_mma(
    const __nv_bfloat16* __restrict__ Ah, const __nv_bfloat16* __restrict__ Al,
    const __nv_bfloat16* __restrict__ Wh, const __nv_bfloat16* __restrict__ Wl,
    const float* __restrict__ bias,
    float* __restrict__ Yf,
    __nv_bfloat16* __restrict__ Yh, __nv_bfloat16* __restrict__ Yl,
    int mode)
{
    __shared__ __align__(16) __nv_bfloat16 sA[2][128][40];
    __shared__ __align__(16) __nv_bfloat16 sW[2][32][136];

    const int tid = threadIdx.x, lane = tid & 31, wid = tid >> 5;
    const int wm = wid >> 2, wn = wid & 3;
    const int m0 = blockIdx.y << 7, n0 = blockIdx.x << 7;

    float c[4][4][4];
    #pragma unroll
    for (int i = 0; i < 4; i++)
        #pragma unroll
        for (int j = 0; j < 4; j++)
            #pragma unroll
            for (int e = 0; e < 4; e++) c[i][j][e] = 0.f;

    const int ar = tid >> 1, ac = (tid & 1) << 4;
    const int wr = tid >> 3, wc = (tid & 7) << 4;
    const int l15 = lane & 15, lh8 = (lane >> 4) << 3;

    for (int kc = 0; kc < 32; kc++) {
        const int k0 = kc << 5;
        uint4 a0 = *(const uint4*)(Ah + (size_t)(m0 + ar) * 1024 + k0 + ac);
        uint4 a1 = *(const uint4*)(Ah + (size_t)(m0 + ar) * 1024 + k0 + ac + 8);
        uint4 b0 = *(const uint4*)(Al + (size_t)(m0 + ar) * 1024 + k0 + ac);
        uint4 b1 = *(const uint4*)(Al + (size_t)(m0 + ar) * 1024 + k0 + ac + 8);
        uint4 w0 = *(const uint4*)(Wh + (size_t)(k0 + wr) * 1024 + n0 + wc);
        uint4 w1 = *(const uint4*)(Wh + (size_t)(k0 + wr) * 1024 + n0 + wc + 8);
        uint4 x0 = *(const uint4*)(Wl + (size_t)(k0 + wr) * 1024 + n0 + wc);
        uint4 x1 = *(const uint4*)(Wl + (size_t)(k0 + wr) * 1024 + n0 + wc + 8);
        __syncthreads();
        *(uint4*)&sA[0][ar][ac]   = a0;  *(uint4*)&sA[0][ar][ac+8] = a1;
        *(uint4*)&sA[1][ar][ac]   = b0;  *(uint4*)&sA[1][ar][ac+8] = b1;
        *(uint4*)&sW[0][wr][wc]   = w0;  *(uint4*)&sW[0][wr][wc+8] = w1;
        *(uint4*)&sW[1][wr][wc]   = x0;  *(uint4*)&sW[1][wr][wc+8] = x1;
        __syncthreads();

        #pragma unroll
        for (int kk = 0; kk < 32; kk += 16) {
            unsigned a[4][4], bh_[4][2], bl_[4][2], t4[4];
            #pragma unroll
            for (int mi = 0; mi < 4; mi++)
                ldsm4(a[mi], smem_u32(&sA[0][wm*64 + mi*16 + l15][kk + lh8]));
            #pragma unroll
            for (int p = 0; p < 2; p++) {
                ldsm4t(t4, smem_u32(&sW[0][kk + l15][wn*32 + p*16 + lh8]));
                bh_[2*p][0]=t4[0]; bh_[2*p][1]=t4[1];
                bh_[2*p+1][0]=t4[2]; bh_[2*p+1][1]=t4[3];
                ldsm4t(t4, smem_u32(&sW[1][kk + l15][wn*32 + p*16 + lh8]));
                bl_[2*p][0]=t4[0]; bl_[2*p][1]=t4[1];
                bl_[2*p+1][0]=t4[2]; bl_[2*p+1][1]=t4[3];
            }
            #pragma unroll
            for (int mi = 0; mi < 4; mi++)
                #pragma unroll
                for (int ni = 0; ni < 4; ni++) mma_bf(c[mi][ni], a[mi], bh_[ni]);
            #pragma unroll
            for (int mi = 0; mi < 4; mi++)
                #pragma unroll
                for (int ni = 0; ni < 4; ni++) mma_bf(c[mi][ni], a[mi], bl_[ni]);
            #pragma unroll
            for (int mi = 0; mi < 4; mi++)
                ldsm4(a[mi], smem_u32(&sA[1][wm*64 + mi*16 + l15][kk + lh8]));
            #pragma unroll
            for (int mi = 0; mi < 4; mi++)
                #pragma unroll
                for (int ni = 0; ni < 4; ni++) mma_bf(c[mi][ni], a[mi], bh_[ni]);
        }
    }

    // Epilogue
    const int rA = lane >> 2, c2 = (lane & 3) << 1;
    #pragma unroll
    for (int mi = 0; mi < 4; mi++) {
        const int rowA = m0 + wm*64 + mi*16 + rA;
        const int rowB = rowA + 8;
        int pA = rowA & (T_-1), pB = rowB & (T_-1);
        if (mode == 1) { pA = g_pos[rowA]; pB = g_pos[rowB]; }
        #pragma unroll
        for (int ni = 0; ni < 4; ni++) {
            const int col = n0 + wn*32 + ni*8 + c2;
            float2 bb = *(const float2*)(bias + col);
            float v00 = c[mi][ni][0] + bb.x, v01 = c[mi][ni][1] + bb.y;
            float v10 = c[mi][ni][2] + bb.x, v11 = c[mi][ni][3] + bb.y;
            if (mode == 2) {
                float2 w0; w0.x = v00; w0.y = v01;
                float2 w1; w1.x = v10; w1.y = v11;
                *(float2*)(Yf + (size_t)rowA * 1024 + col) = w0;
                *(float2*)(Yf + (size_t)rowB * 1024 + col) = w1;
            } else {
                const int hh = col >> 6, dd = col & 63;
                const int bA = rowA >> 11, bB = rowB >> 11;
                __nv_bfloat16 h00 = __float2bfloat16_rn(v00);
                __nv_bfloat16 h01 = __float2bfloat16_rn(v01);
                __nv_bfloat16 h10 = __float2bfloat16_rn(v10);
                __nv_bfloat16 h11 = __float2bfloat16_rn(v11);
                __nv_bfloat162 ph0; ph0.x=h00; ph0.y=h01;
                __nv_bfloat162 ph1; ph1.x=h10; ph1.y=h11;
                __nv_bfloat162 pl0, pl1;
                pl0.x = __float2bfloat16_rn(v00 - __bfloat162float(h00));
                pl0.y = __float2bfloat16_rn(v01 - __bfloat162float(h01));
                pl1.x = __float2bfloat16_rn(v10 - __bfloat162float(h10));
                pl1.y = __float2bfloat16_rn(v11 - __bfloat162float(h11));
                if (pA >= 0) {
                    size_t oA = (((size_t)(bA*H_ + hh))*T_ + pA)*64 + dd;
                    *(__nv_bfloat162*)(Yh + oA) = ph0;
                    *(__nv_bfloat162*)(Yl + oA) = pl0;
                }
                if (pB >= 0) {
                    size_t oB = (((size_t)(bB*H_ + hh))*T_ + pB)*64 + dd;
                    *(__nv_bfloat162*)(Yh + oB) = ph1;
                    *(__nv_bfloat162*)(Yl + oB) = pl1;
                }
            }
        }
    }
}

// ============================================================================
// Flash attention, compacted keys, 64-key tiles, full R3 numerics:
//   S  = Qh·Kh + Qh·Kl + Ql·Kh      (3-stream)
//   PV = Ph·Vh + Ph·Vl + Pl·Vh      (3-stream)
// cp.async double-buffered K/V. Tail guard only (no per-key mask).
// ============================================================================
#define ATT_QH   0                  /* 128 x 72 bf16 = 18432 */
#define ATT_QL   18432
#define ATT_K    36864              /* 2 bufs x (Kh 9216 + Kl 9216) = 36864 */
#define ATT_V    73728              /* 2 bufs x (Vh 9216 + Vl 9216) = 36864 */
#define ATT_PH   110592             /* 128 x 72 bf16 = 18432 */
#define ATT_PL   129024
#define ATT_PSUM 147456             /* 512 floats */
#define ATT_LS   149504             /* 128 floats */
#define ATT_SMEM 150016

__global__ void __launch_bounds__(256) attn_mma()
{
    extern __shared__ __align__(16) char sm[];
    __nv_bfloat16* sQh = (__nv_bfloat16*)(sm + ATT_QH);
    __nv_bfloat16* sQl = (__nv_bfloat16*)(sm + ATT_QL);
    __nv_bfloat16* sPh = (__nv_bfloat16*)(sm + ATT_PH);
    __nv_bfloat16* sPl = (__nv_bfloat16*)(sm + ATT_PL);
    float* psum = (float*)(sm + ATT_PSUM);
    float* l_s  = (float*)(sm + ATT_LS);

    const int tid = threadIdx.x, lane = tid & 31, wid = tid >> 5;
    const int wm = wid >> 2, wn = wid & 3;
    const int qt0 = blockIdx.x << 7;
    const int hh = blockIdx.y, bb = blockIdx.z;
    const size_t base = ((size_t)(bb*H_ + hh)) * T_ * DH_;
    const int nv = g_cnt[bb];
    const int nt = (nv + 63) >> 6;

    const int r = tid >> 1, cofs = (tid & 1) << 5;
    const int l15 = lane & 15, lh8 = (lane >> 4) << 3;
    const int bn  = (lane & 7) + ((lane >> 4) << 3), bk8 = ((lane >> 3) & 1) << 3;
    const int rA0 = lane >> 2, c2 = (lane & 3) << 1;

    const unsigned smK = smem_u32(sm + ATT_K);
    const unsigned smV = smem_u32(sm + ATT_V);

    // cp.async chunk mapping: per 9216B matrix = 512 x 16B chunks, 2/thread
    int ld_row[2], ld_c8[2];
    #pragma unroll
    for (int t = 0; t < 2; t++) {
        int ch = tid + t*256;
        ld_row[t] = ch >> 3;            // 0..63
        ld_c8[t]  = (ch & 7) << 3;      // 0..56
    }

    // Load Q tile hi+lo (persistent)
    {
        const uint4* s1 = (const uint4*)(g_Qh + base + (size_t)(qt0 + r)*64 + cofs);
        uint4* d1 = (uint4*)(sQh + r*72 + cofs);
        d1[0]=s1[0]; d1[1]=s1[1]; d1[2]=s1[2]; d1[3]=s1[3];
        const uint4* s2 = (const uint4*)(g_Ql + base + (size_t)(qt0 + r)*64 + cofs);
        uint4* d2 = (uint4*)(sQl + r*72 + cofs);
        d2[0]=s2[0]; d2[1]=s2[1]; d2[2]=s2[2]; d2[3]=s2[3];
    }
    if (tid < 128) l_s[tid] = 0.f;

    float o[4][2][4];
    #pragma unroll
    for (int i = 0; i < 4; i++)
        #pragma unroll
        for (int j = 0; j < 2; j++)
            #pragma unroll
            for (int e = 0; e < 4; e++) o[i][j][e] = 0.f;

    // Prologue: async-load tile 0 into buf 0
    #pragma unroll
    for (int t = 0; t < 2; t++) {
        unsigned so = (unsigned)((ld_row[t]*72 + ld_c8[t]) * 2);
        size_t go = base + (size_t)ld_row[t]*64 + ld_c8[t];
        CP16(smK + so,         g_Kh + go);
        CP16(smK + 9216u + so, g_Kl + go);
        CP16(smV + so,         g_Vh + go);
        CP16(smV + 9216u + so, g_Vl + go);
    }
    CP_COMMIT();

    for (int kt = 0; kt < nt; kt++) {
        const int buf = kt & 1;
        // Prefetch next K/V tile into the other buffer
        if (kt + 1 < nt) {
            const size_t gofs = base + ((size_t)(kt+1) << 6) * 64;
            const unsigned kb = smK + (buf ^ 1) * 18432u;
            const unsigned vb = smV + (buf ^ 1) * 18432u;
            #pragma unroll
            for (int t = 0; t < 2; t++) {
                unsigned so = (unsigned)((ld_row[t]*72 + ld_c8[t]) * 2);
                size_t go = gofs + (size_t)ld_row[t]*64 + ld_c8[t];
                CP16(kb + so,         g_Kh + go);
                CP16(kb + 9216u + so, g_Kl + go);
                CP16(vb + so,         g_Vh + go);
                CP16(vb + 9216u + so, g_Vl + go);
            }
        }
        CP_COMMIT();
        CP_WAIT1();
        __syncthreads();   // (A) current buffer visible to all warps

        __nv_bfloat16* sKh = (__nv_bfloat16*)(sm + ATT_K + buf*18432);
        __nv_bfloat16* sKl = (__nv_bfloat16*)(sm + ATT_K + buf*18432 + 9216);
        __nv_bfloat16* sVh = (__nv_bfloat16*)(sm + ATT_V + buf*18432);
        __nv_bfloat16* sVl = (__nv_bfloat16*)(sm + ATT_V + buf*18432 + 9216);

        // ---- S = Qh·Kh + Qh·Kl + Ql·Kh  (warp: 64 q x 16 keys) ----
        float s[4][2][4];
        #pragma unroll
        for (int i = 0; i < 4; i++)
            #pragma unroll
            for (int j = 0; j < 2; j++)
                #pragma unroll
                for (int e = 0; e < 4; e++) s[i][j][e] = 0.f;

        #pragma unroll
        for (int kk = 0; kk < 64; kk += 16) {
            unsigned a[4][4], bhf[2][2], blf[2][2], t4[4];
            #pragma unroll
            for (int mi = 0; mi < 4; mi++)
                ldsm4(a[mi], smem_u32(&sQh[(wm*64 + mi*16 + l15)*72 + kk + lh8]));
            ldsm4(t4, smem_u32(&sKh[(wn*16 + bn)*72 + kk + bk8]));
            bhf[0][0]=t4[0]; bhf[0][1]=t4[1]; bhf[1][0]=t4[2]; bhf[1][1]=t4[3];
            ldsm4(t4, smem_u32(&sKl[(wn*16 + bn)*72 + kk + bk8]));
            blf[0][0]=t4[0]; blf[0][1]=t4[1]; blf[1][0]=t4[2]; blf[1][1]=t4[3];
            #pragma unroll
            for (int mi = 0; mi < 4; mi++)
                #pragma unroll
                for (int ni = 0; ni < 2; ni++) mma_bf(s[mi][ni], a[mi], bhf[ni]);
            #pragma unroll
            for (int mi = 0; mi < 4; mi++)
                #pragma unroll
                for (int ni = 0; ni < 2; ni++) mma_bf(s[mi][ni], a[mi], blf[ni]);
            #pragma unroll
            for (int mi = 0; mi < 4; mi++)
                ldsm4(a[mi], smem_u32(&sQl[(wm*64 + mi*16 + l15)*72 + kk + lh8]));
            #pragma unroll
            for (int mi = 0; mi < 4; mi++)
                #pragma unroll
                for (int ni = 0; ni < 2; ni++) mma_bf(s[mi][ni], a[mi], bhf[ni]);
        }

        // ---- p = (col valid) ? exp(s*scale) : 0; row sums; write Ph+Pl ----
        const int k0g = kt << 6;
        #pragma unroll
        for (int mi = 0; mi < 4; mi++) {
            float sumA = 0.f, sumB = 0.f;
            const int rowA = wm*64 + mi*16 + rA0;
            #pragma unroll
            for (int ni = 0; ni < 2; ni++) {
                const int col = wn*16 + ni*8 + c2;
                const bool v0 = (k0g + col)     < nv;
                const bool v1 = (k0g + col + 1) < nv;
                float p00 = v0 ? __expf(s[mi][ni][0]*SCALE_) : 0.f;
                float p01 = v1 ? __expf(s[mi][ni][1]*SCALE_) : 0.f;
                float p10 = v0 ? __expf(s[mi][ni][2]*SCALE_) : 0.f;
                float p11 = v1 ? __expf(s[mi][ni][3]*SCALE_) : 0.f;
                sumA += p00 + p01;  sumB += p10 + p11;
                __nv_bfloat16 h00 = __float2bfloat16_rn(p00);
                __nv_bfloat16 h01 = __float2bfloat16_rn(p01);
                __nv_bfloat16 h10 = __float2bfloat16_rn(p10);
                __nv_bfloat16 h11 = __float2bfloat16_rn(p11);
                __nv_bfloat162 vh0; vh0.x=h00; vh0.y=h01;
                __nv_bfloat162 vh1; vh1.x=h10; vh1.y=h11;
                __nv_bfloat162 vl0, vl1;
                vl0.x = __float2bfloat16_rn(p00 - __bfloat162float(h00));
                vl0.y = __float2bfloat16_rn(p01 - __bfloat162float(h01));
                vl1.x = __float2bfloat16_rn(p10 - __bfloat162float(h10));
                vl1.y = __float2bfloat16_rn(p11 - __bfloat162float(h11));
                *(__nv_bfloat162*)(sPh + rowA*72 + col)      = vh0;
                *(__nv_bfloat162*)(sPh + (rowA+8)*72 + col)  = vh1;
                *(__nv_bfloat162*)(sPl + rowA*72 + col)      = vl0;
                *(__nv_bfloat162*)(sPl + (rowA+8)*72 + col)  = vl1;
            }
            sumA += __shfl_xor_sync(0xffffffffu, sumA, 1);
            sumA += __shfl_xor_sync(0xffffffffu, sumA, 2);
            sumB += __shfl_xor_sync(0xffffffffu, sumB, 1);
            sumB += __shfl_xor_sync(0xffffffffu, sumB, 2);
            if ((lane & 3) == 0) {
                psum[rowA*4 + wn]     = sumA;
                psum[(rowA+8)*4 + wn] = sumB;
            }
        }
        __syncthreads();   // (B)

        if (tid < 128)
            l_s[tid] += psum[tid*4+0] + psum[tid*4+1] + psum[tid*4+2] + psum[tid*4+3];

        // ---- O += Ph·Vh + Ph·Vl + Pl·Vh  (warp: 64 q x 16 dh) ----
        #pragma unroll
        for (int kk = 0; kk < 64; kk += 16) {
            unsigned pa[4][4], vhf[2][2], vlf[2][2], t4[4];
            #pragma unroll
            for (int mi = 0; mi < 4; mi++)
                ldsm4(pa[mi], smem_u32(&sPh[(wm*64 + mi*16 + l15)*72 + kk + lh8]));
            ldsm4t(t4, smem_u32(&sVh[(kk + l15)*72 + wn*16 + lh8]));
            vhf[0][0]=t4[0]; vhf[0][1]=t4[1]; vhf[1][0]=t4[2]; vhf[1][1]=t4[3];
            ldsm4t(t4, smem_u32(&sVl[(kk + l15)*72 + wn*16 + lh8]));
            vlf[0][0]=t4[0]; vlf[0][1]=t4[1]; vlf[1][0]=t4[2]; vlf[1][1]=t4[3];
            #pragma unroll
            for (int mi = 0; mi < 4; mi++)
                #pragma unroll
                for (int ni = 0; ni < 2; ni++) mma_bf(o[mi][ni], pa[mi], vhf[ni]);
            #pragma unroll
            for (int mi = 0; mi < 4; mi++)
                #pragma unroll
                for (int ni = 0; ni < 2; ni++) mma_bf(o[mi][ni], pa[mi], vlf[ni]);
            #pragma unroll
            for (int mi = 0; mi < 4; mi++)
                ldsm4(pa[mi], smem_u32(&sPl[(wm*64 + mi*16 + l15)*72 + kk + lh8]));
            #pragma unroll
            for (int mi = 0; mi < 4; mi++)
                #pragma unroll
                for (int ni = 0; ni < 2; ni++) mma_bf(o[mi][ni], pa[mi], vhf[ni]);
        }
        __syncthreads();   // (C)
    }

    // ---- normalize + write context (fp32) ----
    #pragma unroll
    for (int mi = 0; mi < 4; mi++) {
        const int rowA = wm*64 + mi*16 + rA0, rowB = rowA + 8;
        const float invA = 1.f / l_s[rowA], invB = 1.f / l_s[rowB];
        #pragma unroll
        for (int ni = 0; ni < 2; ni++) {
            const int col = wn*16 + ni*8 + c2;
            float2 w0; w0.x = o[mi][ni][0]*invA; w0.y = o[mi][ni][1]*invA;
            float2 w1; w1.x = o[mi][ni][2]*invB; w1.y = o[mi][ni][3]*invB;
            *(float2*)(g_CTX + (size_t)(bb*T_ + qt0 + rowA)*D_ + hh*64 + col) = w0;
            *(float2*)(g_CTX + (size_t)(bb*T_ + qt0 + rowB)*D_ + hh*64 + col) = w1;
        }
    }
}

// ============================================================================
extern "C" void kernel_launch(void* const* d_in, const int* in_sizes, int n_in,
                              void* d_out, int out_size)
{
    const float* q  = (const float*)d_in[0];
    const float* k  = (const float*)d_in[1];
    const float* v  = (const float*)d_in[2];
    const int*  mk  = (const int*)  d_in[3];
    const float* Wq = (const float*)d_in[4];
    const float* bq = (const float*)d_in[5];
    const float* Wk = (const float*)d_in[6];
    const float* bk = (const float*)d_in[7];
    const float* Wv = (const float*)d_in[8];
    const float* bv = (const float*)d_in[9];
    const float* Wo = (const float*)d_in[10];
    const float* bo = (const float*)d_in[11];
    float* out = (float*)d_out;

    float* pCTX;
    __nv_bfloat16 *pAh, *pAl, *pWh, *pWl, *pQh, *pQl, *pKh, *pKl, *pVh, *pVl;
    cudaGetSymbolAddress((void**)&pCTX, g_CTX);
    cudaGetSymbolAddress((void**)&pAh, g_Ah);
    cudaGetSymbolAddress((void**)&pAl, g_Al);
    cudaGetSymbolAddress((void**)&pWh, g_Wh);
    cudaGetSymbolAddress((void**)&pWl, g_Wl);
    cudaGetSymbolAddress((void**)&pQh, g_Qh);
    cudaGetSymbolAddress((void**)&pQl, g_Ql);
    cudaGetSymbolAddress((void**)&pKh, g_Kh);
    cudaGetSymbolAddress((void**)&pKl, g_Kl);
    cudaGetSymbolAddress((void**)&pVh, g_Vh);
    cudaGetSymbolAddress((void**)&pVl, g_Vl);

    cudaFuncSetAttribute(attn_mma,
                         cudaFuncAttributeMaxDynamicSharedMemorySize, ATT_SMEM);

    dim3 blk(256);
    dim3 gG(8, 32);

    scan_mask<<<B_, 1024>>>(mk);

    // Q projection (hi+lo, [B,H,T,64] scatter)
    conv_split<<<4096, blk>>>(q, pAh, pAl, 1048576);
    conv_split<<<1024, blk>>>(Wq, pWh, pWl, 262144);
    gemm_mma<<<gG, blk>>>(pAh, pAl, pWh, pWl, bq, nullptr, pQh, pQl, 0);
    // K projection (compacted hi+lo)
    conv_split<<<4096, blk>>>(k, pAh, pAl, 1048576);
    conv_split<<<1024, blk>>>(Wk, pWh, pWl, 262144);
    gemm_mma<<<gG, blk>>>(pAh, pAl, pWh, pWl, bk, nullptr, pKh, pKl, 1);
    // V projection (compacted hi+lo)
    conv_split<<<4096, blk>>>(v, pAh, pAl, 1048576);
    conv_split<<<1024, blk>>>(Wv, pWh, pWl, 262144);
    gemm_mma<<<gG, blk>>>(pAh, pAl, pWh, pWl, bv, nullptr, pVh, pVl, 1);
    // Attention over compacted keys
    attn_mma<<<dim3(16, 16, 2), blk, ATT_SMEM>>>();
    // Output projection
    conv_split<<<4096, blk>>>(pCTX, pAh, pAl, 1048576);
    conv_split<<<1024, blk>>>(Wo, pWh, pWl, 262144);
    gemm_mma<<<gG, blk>>>(pAh, pAl, pWh, pWl, bo, out, nullptr, nullptr, 2);
}